// round 1
// baseline (speedup 1.0000x reference)
#include <cuda_runtime.h>
#include <cstdint>

#define MAXN 100000
#define EPS_LN 1e-5f

// ---------------- scratch (device globals; no allocation allowed) ----------
__device__ float g_deg[MAXN];                     // deg, then 1/max(deg,1)
__device__ float g_agg[(size_t)MAXN * 128];       // scatter accumulator
__device__ float g_hA[(size_t)MAXN * 128];        // h0, then t2
__device__ float g_hB[(size_t)MAXN * 128];        // h1

typedef unsigned long long u64;
typedef unsigned int u32;

// ---------------- packed fp32x2 helpers (Blackwell FFMA2 pipe) -------------
__device__ __forceinline__ u64 pack2(float a, float b) {
    u64 r;
    asm("mov.b64 %0, {%1, %2};" : "=l"(r) : "r"(__float_as_uint(a)), "r"(__float_as_uint(b)));
    return r;
}
__device__ __forceinline__ void unpack2(u64 v, float& a, float& b) {
    u32 lo, hi;
    asm("mov.b64 {%0, %1}, %2;" : "=r"(lo), "=r"(hi) : "l"(v));
    a = __uint_as_float(lo); b = __uint_as_float(hi);
}
__device__ __forceinline__ void fma2(u64& d, u64 a, u64 b) {
    asm("fma.rn.f32x2 %0, %1, %2, %0;" : "+l"(d) : "l"(a), "l"(b));
}

__device__ __forceinline__ void red_add_v4(float* p, float4 v) {
    asm volatile("red.global.add.v4.f32 [%0], {%1, %2, %3, %4};"
                 :: "l"(p), "f"(v.x), "f"(v.y), "f"(v.z), "f"(v.w) : "memory");
}

// ---------------- tiny utility kernels -------------------------------------
__global__ void k_zero(float* __restrict__ p, long n4) {
    long i = blockIdx.x * (long)blockDim.x + threadIdx.x;
    float4 z = make_float4(0.f, 0.f, 0.f, 0.f);
    for (; i < n4; i += (long)gridDim.x * blockDim.x)
        reinterpret_cast<float4*>(p)[i] = z;
}

__global__ void k_deg(const int* __restrict__ dst, float* __restrict__ deg, int E) {
    int i = blockIdx.x * blockDim.x + threadIdx.x;
    if (i < E) atomicAdd(&deg[dst[i]], 1.0f);
}

__global__ void k_rdeg(float* __restrict__ deg, int n) {
    int i = blockIdx.x * blockDim.x + threadIdx.x;
    if (i < n) deg[i] = 1.0f / fmaxf(deg[i], 1.0f);
}

// scatter-sum of 128-wide rows: one warp per edge, red.v4 per lane
__global__ void __launch_bounds__(256) k_scatter128(
    const float* __restrict__ feat, const int* __restrict__ src,
    const int* __restrict__ dst, float* __restrict__ agg, int E)
{
    int w = (blockIdx.x * 256 + threadIdx.x) >> 5;
    int lane = threadIdx.x & 31;
    if (w >= E) return;
    int s = __ldg(&src[w]);
    int d = __ldg(&dst[w]);
    float4 v = *reinterpret_cast<const float4*>(feat + (size_t)s * 128 + lane * 4);
    red_add_v4(agg + (size_t)d * 128 + lane * 4, v);
}

// scatter-sum of cols [64,128) of t2 into a 64-wide accumulator: half-warp/edge
__global__ void __launch_bounds__(256) k_scatter64(
    const float* __restrict__ t2, const int* __restrict__ src,
    const int* __restrict__ dst, float* __restrict__ agg, int E)
{
    int gt = blockIdx.x * 256 + threadIdx.x;
    int e = gt >> 4;
    int l = gt & 15;
    if (e >= E) return;
    int s = __ldg(&src[e]);
    int d = __ldg(&dst[e]);
    float4 v = *reinterpret_cast<const float4*>(t2 + (size_t)s * 128 + 64 + l * 4);
    red_add_v4(agg + (size_t)d * 64 + l * 4, v);
}

// ---------------- fused GEMM (K=256: [x | agg*rdeg]) + bias + LN + ReLU ----
// BM=64, BN=128, BK=16, 256 threads, thread tile 8x4; accumulate in f32x2.
__global__ void __launch_bounds__(256) k_gemm_ln(
    const float* __restrict__ X, const float* __restrict__ AGG,
    const float* __restrict__ rdeg,
    const float* __restrict__ Wr, const float* __restrict__ Wn,
    const float* __restrict__ bias, const float* __restrict__ gamma,
    const float* __restrict__ beta,
    float* __restrict__ out, int n)
{
    __shared__ float2 As2[16][64];   // A value duplicated into both halves
    __shared__ float  Bs[16][128];

    int tid = threadIdx.x;
    int tx = tid & 31, ty = tid >> 5;
    int base = blockIdx.x * 64;

    int ar  = tid >> 2;             // 0..63 row within tile
    int ac4 = (tid & 3) << 2;       // 0,4,8,12 k within tile
    int arow = base + ar;
    bool arok = arow < n;
    float rd = arok ? rdeg[arow] : 0.f;

    int kb = tid >> 4;              // 0..15 k within tile
    int jb = (tid & 15) << 3;       // 0..120 col

    u64 acc[8][2];
    #pragma unroll
    for (int i = 0; i < 8; i++) { acc[i][0] = 0ull; acc[i][1] = 0ull; }

    #pragma unroll 1
    for (int kt = 0; kt < 16; kt++) {
        int ko = kt << 4;
        float4 av = make_float4(0.f, 0.f, 0.f, 0.f);
        if (arok) {
            if (ko < 128) {
                av = *reinterpret_cast<const float4*>(X + (size_t)arow * 128 + ko + ac4);
            } else {
                av = *reinterpret_cast<const float4*>(AGG + (size_t)arow * 128 + (ko - 128) + ac4);
                av.x *= rd; av.y *= rd; av.z *= rd; av.w *= rd;
            }
        }
        int kg = ko + kb;
        const float* Wp = (kg < 128) ? (Wr + (size_t)kg * 128)
                                     : (Wn + (size_t)(kg - 128) * 128);
        float4 bv0 = *reinterpret_cast<const float4*>(Wp + jb);
        float4 bv1 = *reinterpret_cast<const float4*>(Wp + jb + 4);

        __syncthreads();
        As2[ac4 + 0][ar] = make_float2(av.x, av.x);
        As2[ac4 + 1][ar] = make_float2(av.y, av.y);
        As2[ac4 + 2][ar] = make_float2(av.z, av.z);
        As2[ac4 + 3][ar] = make_float2(av.w, av.w);
        *reinterpret_cast<float4*>(&Bs[kb][jb])     = bv0;
        *reinterpret_cast<float4*>(&Bs[kb][jb + 4]) = bv1;
        __syncthreads();

        #pragma unroll
        for (int kk = 0; kk < 16; kk++) {
            u64 a[8];
            #pragma unroll
            for (int i = 0; i < 8; i++)
                a[i] = *reinterpret_cast<const u64*>(&As2[kk][ty * 8 + i]);
            u64 b01 = *reinterpret_cast<const u64*>(&Bs[kk][tx * 4]);
            u64 b23 = *reinterpret_cast<const u64*>(&Bs[kk][tx * 4 + 2]);
            #pragma unroll
            for (int i = 0; i < 8; i++) {
                fma2(acc[i][0], a[i], b01);
                fma2(acc[i][1], a[i], b23);
            }
        }
    }

    // epilogue: +bias, LayerNorm over the 128 cols (one warp owns a row), ReLU
    float4 bb = *reinterpret_cast<const float4*>(bias  + (tx << 2));
    float4 gg = *reinterpret_cast<const float4*>(gamma + (tx << 2));
    float4 ee = *reinterpret_cast<const float4*>(beta  + (tx << 2));

    #pragma unroll
    for (int i = 0; i < 8; i++) {
        int row = base + ty * 8 + i;
        float v0, v1, v2, v3;
        unpack2(acc[i][0], v0, v1);
        unpack2(acc[i][1], v2, v3);
        v0 += bb.x; v1 += bb.y; v2 += bb.z; v3 += bb.w;
        float s1 = v0 + v1 + v2 + v3;
        float s2 = v0 * v0 + v1 * v1 + v2 * v2 + v3 * v3;
        #pragma unroll
        for (int o = 16; o > 0; o >>= 1) {
            s1 += __shfl_xor_sync(0xffffffffu, s1, o);
            s2 += __shfl_xor_sync(0xffffffffu, s2, o);
        }
        float mu = s1 * (1.0f / 128.0f);
        float var = s2 * (1.0f / 128.0f) - mu * mu;
        float rstd = rsqrtf(var + EPS_LN);
        if (row < n) {
            float4 o4;
            o4.x = fmaxf((v0 - mu) * rstd * gg.x + ee.x, 0.f);
            o4.y = fmaxf((v1 - mu) * rstd * gg.y + ee.y, 0.f);
            o4.z = fmaxf((v2 - mu) * rstd * gg.z + ee.z, 0.f);
            o4.w = fmaxf((v3 - mu) * rstd * gg.w + ee.w, 0.f);
            *reinterpret_cast<float4*>(out + (size_t)row * 128 + (tx << 2)) = o4;
        }
    }
}

// ---------------- layer-2 GEMM: t2 = h1 @ [Wr2 | Wn2]  (K=128, BN=128) -----
__global__ void __launch_bounds__(256) k_gemm2(
    const float* __restrict__ X,
    const float* __restrict__ Wr2, const float* __restrict__ Wn2,
    float* __restrict__ out, int n)
{
    __shared__ float2 As2[16][64];
    __shared__ float  Bs[16][128];

    int tid = threadIdx.x;
    int tx = tid & 31, ty = tid >> 5;
    int base = blockIdx.x * 64;

    int ar  = tid >> 2;
    int ac4 = (tid & 3) << 2;
    int arow = base + ar;
    bool arok = arow < n;

    int kb = tid >> 4;
    int jb = (tid & 15) << 3;

    u64 acc[8][2];
    #pragma unroll
    for (int i = 0; i < 8; i++) { acc[i][0] = 0ull; acc[i][1] = 0ull; }

    #pragma unroll 1
    for (int kt = 0; kt < 8; kt++) {
        int ko = kt << 4;
        float4 av = make_float4(0.f, 0.f, 0.f, 0.f);
        if (arok)
            av = *reinterpret_cast<const float4*>(X + (size_t)arow * 128 + ko + ac4);
        int kg = ko + kb;
        const float* Wp = (jb < 64) ? (Wr2 + (size_t)kg * 64 + jb)
                                    : (Wn2 + (size_t)kg * 64 + (jb - 64));
        float4 bv0 = *reinterpret_cast<const float4*>(Wp);
        float4 bv1 = *reinterpret_cast<const float4*>(Wp + 4);

        __syncthreads();
        As2[ac4 + 0][ar] = make_float2(av.x, av.x);
        As2[ac4 + 1][ar] = make_float2(av.y, av.y);
        As2[ac4 + 2][ar] = make_float2(av.z, av.z);
        As2[ac4 + 3][ar] = make_float2(av.w, av.w);
        *reinterpret_cast<float4*>(&Bs[kb][jb])     = bv0;
        *reinterpret_cast<float4*>(&Bs[kb][jb + 4]) = bv1;
        __syncthreads();

        #pragma unroll
        for (int kk = 0; kk < 16; kk++) {
            u64 a[8];
            #pragma unroll
            for (int i = 0; i < 8; i++)
                a[i] = *reinterpret_cast<const u64*>(&As2[kk][ty * 8 + i]);
            u64 b01 = *reinterpret_cast<const u64*>(&Bs[kk][tx * 4]);
            u64 b23 = *reinterpret_cast<const u64*>(&Bs[kk][tx * 4 + 2]);
            #pragma unroll
            for (int i = 0; i < 8; i++) {
                fma2(acc[i][0], a[i], b01);
                fma2(acc[i][1], a[i], b23);
            }
        }
    }

    #pragma unroll
    for (int i = 0; i < 8; i++) {
        int row = base + ty * 8 + i;
        if (row < n) {
            float v0, v1, v2, v3;
            unpack2(acc[i][0], v0, v1);
            unpack2(acc[i][1], v2, v3);
            float4 o4 = make_float4(v0, v1, v2, v3);
            *reinterpret_cast<float4*>(out + (size_t)row * 128 + (tx << 2)) = o4;
        }
    }
}

// ---------------- final: out = log_softmax(t2[:, :64] + agg/deg + b2) ------
__global__ void __launch_bounds__(256) k_final(
    const float* __restrict__ t2, const float* __restrict__ agg,
    const float* __restrict__ rdeg, const float* __restrict__ b2,
    float* __restrict__ out, int n)
{
    int w = (blockIdx.x * 256 + threadIdx.x) >> 5;
    int lane = threadIdx.x & 31;
    if (w >= n) return;
    float rd = rdeg[w];
    float va = t2[(size_t)w * 128 + lane]      + agg[(size_t)w * 64 + lane]      * rd + __ldg(&b2[lane]);
    float vb = t2[(size_t)w * 128 + 32 + lane] + agg[(size_t)w * 64 + 32 + lane] * rd + __ldg(&b2[32 + lane]);
    float m = fmaxf(va, vb);
    #pragma unroll
    for (int o = 16; o > 0; o >>= 1)
        m = fmaxf(m, __shfl_xor_sync(0xffffffffu, m, o));
    float se = expf(va - m) + expf(vb - m);
    #pragma unroll
    for (int o = 16; o > 0; o >>= 1)
        se += __shfl_xor_sync(0xffffffffu, se, o);
    float ls = m + logf(se);
    out[(size_t)w * 64 + lane]      = va - ls;
    out[(size_t)w * 64 + 32 + lane] = vb - ls;
}

// ---------------- launcher --------------------------------------------------
extern "C" void kernel_launch(void* const* d_in, const int* in_sizes, int n_in,
                              void* d_out, int out_size)
{
    const float* x   = (const float*)d_in[0];
    const int*  esrc = (const int*)d_in[1];
    const int*  edst = (const int*)d_in[2];
    const float* Wr0 = (const float*)d_in[3];
    const float* Wn0 = (const float*)d_in[4];
    const float* b0  = (const float*)d_in[5];
    const float* g0  = (const float*)d_in[6];
    const float* be0 = (const float*)d_in[7];
    const float* Wr1 = (const float*)d_in[8];
    const float* Wn1 = (const float*)d_in[9];
    const float* b1  = (const float*)d_in[10];
    const float* g1  = (const float*)d_in[11];
    const float* be1 = (const float*)d_in[12];
    const float* Wr2 = (const float*)d_in[13];
    const float* Wn2 = (const float*)d_in[14];
    const float* b2  = (const float*)d_in[15];
    float* out = (float*)d_out;

    int n = in_sizes[0] / 128;
    int E = in_sizes[1];
    if (n > MAXN) n = MAXN;

    float *deg, *agg, *hA, *hB;
    cudaGetSymbolAddress((void**)&deg, g_deg);
    cudaGetSymbolAddress((void**)&agg, g_agg);
    cudaGetSymbolAddress((void**)&hA,  g_hA);
    cudaGetSymbolAddress((void**)&hB,  g_hB);

    int gb = (n + 63) / 64;

    // degree (once; same edge list each layer), then invert
    k_zero<<<256, 256>>>(deg, n / 4);
    k_zero<<<1024, 256>>>(agg, (long)n * 32);
    k_deg<<<(E + 255) / 256, 256>>>(edst, deg, E);
    k_rdeg<<<(n + 255) / 256, 256>>>(deg, n);

    // layer 0
    k_scatter128<<<(E + 7) / 8, 256>>>(x, esrc, edst, agg, E);
    k_gemm_ln<<<gb, 256>>>(x, agg, deg, Wr0, Wn0, b0, g0, be0, hA, n);

    // layer 1
    k_zero<<<1024, 256>>>(agg, (long)n * 32);
    k_scatter128<<<(E + 7) / 8, 256>>>(hA, esrc, edst, agg, E);
    k_gemm_ln<<<gb, 256>>>(hA, agg, deg, Wr1, Wn1, b1, g1, be1, hB, n);

    // layer 2: t2 = h1 @ [Wr2 | Wn2]; aggregate the Wn half post-GEMM (64-wide)
    k_gemm2<<<gb, 256>>>(hB, Wr2, Wn2, hA, n);
    k_zero<<<1024, 256>>>(agg, (long)n * 16);
    k_scatter64<<<(E + 15) / 16, 256>>>(hA, esrc, edst, agg, E);
    k_final<<<(n + 7) / 8, 256>>>(hA, agg, deg, b2, out, n);
}

// round 2
// speedup vs baseline: 1.1259x; 1.1259x over previous
#include <cuda_runtime.h>
#include <cstdint>

#define MAXN 100000
#define MAXE 1600000
#define EPS_LN 1e-5f

// ---------------- scratch (device globals; no allocation allowed) ----------
__device__ int   g_degi[MAXN];
__device__ int   g_off[MAXN + 1];
__device__ int   g_cursor[MAXN];
__device__ int   g_csr[MAXE];                     // src ids grouped by dst
__device__ float g_rdeg[MAXN];                    // 1/max(deg,1)
__device__ float g_agg[(size_t)MAXN * 128];       // mean-agg result
__device__ float g_hA[(size_t)MAXN * 128];        // h0, then t2
__device__ float g_hB[(size_t)MAXN * 128];        // h1

typedef unsigned long long u64;
typedef unsigned int u32;

// ---------------- packed fp32x2 helpers (Blackwell FFMA2 pipe) -------------
__device__ __forceinline__ void unpack2(u64 v, float& a, float& b) {
    u32 lo, hi;
    asm("mov.b64 {%0, %1}, %2;" : "=r"(lo), "=r"(hi) : "l"(v));
    a = __uint_as_float(lo); b = __uint_as_float(hi);
}
__device__ __forceinline__ void fma2(u64& d, u64 a, u64 b) {
    asm("fma.rn.f32x2 %0, %1, %2, %0;" : "+l"(d) : "l"(a), "l"(b));
}

// ---------------- CSR build --------------------------------------------------
__global__ void k_zeroi(int* __restrict__ p, int n) {
    int i = blockIdx.x * blockDim.x + threadIdx.x;
    if (i < n) p[i] = 0;
}

__global__ void k_count(const int* __restrict__ dst, int* __restrict__ deg, int E) {
    int i = blockIdx.x * blockDim.x + threadIdx.x;
    if (i < E) atomicAdd(&deg[dst[i]], 1);
}

// single-block exclusive scan over deg -> off/cursor, plus rdeg
__global__ void __launch_bounds__(1024) k_scan(
    const int* __restrict__ deg, int* __restrict__ off,
    int* __restrict__ cursor, float* __restrict__ rdeg, int n)
{
    __shared__ int sb[1024];
    int tid = threadIdx.x;
    int chunk = (n + 1023) >> 10;
    int s = tid * chunk;
    int e = min(s + chunk, n);
    int sum = 0;
    for (int i = s; i < e; i++) sum += deg[i];
    sb[tid] = sum;
    __syncthreads();
    int val = sum;
    for (int o = 1; o < 1024; o <<= 1) {
        int t = (tid >= o) ? sb[tid - o] : 0;
        __syncthreads();
        sb[tid] += t;
        __syncthreads();
    }
    int base = sb[tid] - val;   // exclusive prefix
    for (int i = s; i < e; i++) {
        int d = deg[i];
        off[i] = base;
        cursor[i] = base;
        rdeg[i] = 1.0f / fmaxf((float)d, 1.0f);
        base += d;
    }
    if (tid == 1023) off[n] = base;  // == E (sum of all)
}

__global__ void k_fill(const int* __restrict__ src, const int* __restrict__ dst,
                       int* __restrict__ cursor, int* __restrict__ csr, int E)
{
    int i = blockIdx.x * blockDim.x + threadIdx.x;
    if (i < E) {
        int p = atomicAdd(&cursor[dst[i]], 1);
        csr[p] = src[i];
    }
}

// ---------------- gather-based mean aggregation (no atomics) ---------------
// one warp per dst node; each lane owns 4 cols; 2-deep unroll for MLP
__global__ void __launch_bounds__(256) k_agg128(
    const float* __restrict__ feat, const int* __restrict__ csr,
    const int* __restrict__ off, const float* __restrict__ rdeg,
    float* __restrict__ agg, int n)
{
    int w = (blockIdx.x * 256 + threadIdx.x) >> 5;
    int lane = threadIdx.x & 31;
    if (w >= n) return;
    int s0 = off[w], s1 = off[w + 1];
    float4 a0 = make_float4(0.f, 0.f, 0.f, 0.f);
    float4 a1 = make_float4(0.f, 0.f, 0.f, 0.f);
    int e = s0;
    for (; e + 2 <= s1; e += 2) {
        int i0 = csr[e], i1 = csr[e + 1];
        float4 v0 = *reinterpret_cast<const float4*>(feat + (size_t)i0 * 128 + lane * 4);
        float4 v1 = *reinterpret_cast<const float4*>(feat + (size_t)i1 * 128 + lane * 4);
        a0.x += v0.x; a0.y += v0.y; a0.z += v0.z; a0.w += v0.w;
        a1.x += v1.x; a1.y += v1.y; a1.z += v1.z; a1.w += v1.w;
    }
    if (e < s1) {
        int i0 = csr[e];
        float4 v0 = *reinterpret_cast<const float4*>(feat + (size_t)i0 * 128 + lane * 4);
        a0.x += v0.x; a0.y += v0.y; a0.z += v0.z; a0.w += v0.w;
    }
    float r = rdeg[w];
    float4 o4;
    o4.x = (a0.x + a1.x) * r;
    o4.y = (a0.y + a1.y) * r;
    o4.z = (a0.z + a1.z) * r;
    o4.w = (a0.w + a1.w) * r;
    *reinterpret_cast<float4*>(agg + (size_t)w * 128 + lane * 4) = o4;
}

// cols [64,128) of t2 -> 64-wide mean agg; half-warp per edge stream
__global__ void __launch_bounds__(256) k_agg64(
    const float* __restrict__ t2, const int* __restrict__ csr,
    const int* __restrict__ off, const float* __restrict__ rdeg,
    float* __restrict__ agg, int n)
{
    int w = (blockIdx.x * 256 + threadIdx.x) >> 5;
    int lane = threadIdx.x & 31;
    if (w >= n) return;
    int half = lane >> 4, l = lane & 15;
    int s0 = off[w], s1 = off[w + 1];
    float4 a = make_float4(0.f, 0.f, 0.f, 0.f);
    for (int e = s0 + half; e < s1; e += 2) {
        int i0 = csr[e];
        float4 v = *reinterpret_cast<const float4*>(t2 + (size_t)i0 * 128 + 64 + l * 4);
        a.x += v.x; a.y += v.y; a.z += v.z; a.w += v.w;
    }
    a.x += __shfl_xor_sync(0xffffffffu, a.x, 16);
    a.y += __shfl_xor_sync(0xffffffffu, a.y, 16);
    a.z += __shfl_xor_sync(0xffffffffu, a.z, 16);
    a.w += __shfl_xor_sync(0xffffffffu, a.w, 16);
    if (half == 0) {
        float r = rdeg[w];
        float4 o4 = make_float4(a.x * r, a.y * r, a.z * r, a.w * r);
        *reinterpret_cast<float4*>(agg + (size_t)w * 64 + l * 4) = o4;
    }
}

// ---------------- fused GEMM (K=256: [x | agg]) + bias + LN + ReLU ---------
// BM=64, BN=128, BK=16, 256 threads, thread tile 8x4; accumulate in f32x2.
__global__ void __launch_bounds__(256) k_gemm_ln(
    const float* __restrict__ X, const float* __restrict__ AGG,
    const float* __restrict__ Wr, const float* __restrict__ Wn,
    const float* __restrict__ bias, const float* __restrict__ gamma,
    const float* __restrict__ beta,
    float* __restrict__ out, int n)
{
    __shared__ float2 As2[16][64];   // A value duplicated into both halves
    __shared__ float  Bs[16][128];

    int tid = threadIdx.x;
    int tx = tid & 31, ty = tid >> 5;
    int base = blockIdx.x * 64;

    int ar  = tid >> 2;             // 0..63 row within tile
    int ac4 = (tid & 3) << 2;       // 0,4,8,12 k within tile
    int arow = base + ar;
    bool arok = arow < n;

    int kb = tid >> 4;              // 0..15 k within tile
    int jb = (tid & 15) << 3;       // 0..120 col

    u64 acc[8][2];
    #pragma unroll
    for (int i = 0; i < 8; i++) { acc[i][0] = 0ull; acc[i][1] = 0ull; }

    #pragma unroll 1
    for (int kt = 0; kt < 16; kt++) {
        int ko = kt << 4;
        float4 av = make_float4(0.f, 0.f, 0.f, 0.f);
        if (arok) {
            if (ko < 128)
                av = *reinterpret_cast<const float4*>(X + (size_t)arow * 128 + ko + ac4);
            else
                av = *reinterpret_cast<const float4*>(AGG + (size_t)arow * 128 + (ko - 128) + ac4);
        }
        int kg = ko + kb;
        const float* Wp = (kg < 128) ? (Wr + (size_t)kg * 128)
                                     : (Wn + (size_t)(kg - 128) * 128);
        float4 bv0 = *reinterpret_cast<const float4*>(Wp + jb);
        float4 bv1 = *reinterpret_cast<const float4*>(Wp + jb + 4);

        __syncthreads();
        As2[ac4 + 0][ar] = make_float2(av.x, av.x);
        As2[ac4 + 1][ar] = make_float2(av.y, av.y);
        As2[ac4 + 2][ar] = make_float2(av.z, av.z);
        As2[ac4 + 3][ar] = make_float2(av.w, av.w);
        *reinterpret_cast<float4*>(&Bs[kb][jb])     = bv0;
        *reinterpret_cast<float4*>(&Bs[kb][jb + 4]) = bv1;
        __syncthreads();

        #pragma unroll
        for (int kk = 0; kk < 16; kk++) {
            u64 a[8];
            #pragma unroll
            for (int i = 0; i < 8; i++)
                a[i] = *reinterpret_cast<const u64*>(&As2[kk][ty * 8 + i]);
            u64 b01 = *reinterpret_cast<const u64*>(&Bs[kk][tx * 4]);
            u64 b23 = *reinterpret_cast<const u64*>(&Bs[kk][tx * 4 + 2]);
            #pragma unroll
            for (int i = 0; i < 8; i++) {
                fma2(acc[i][0], a[i], b01);
                fma2(acc[i][1], a[i], b23);
            }
        }
    }

    // epilogue: +bias, LayerNorm over the 128 cols (one warp owns a row), ReLU
    float4 bb = *reinterpret_cast<const float4*>(bias  + (tx << 2));
    float4 gg = *reinterpret_cast<const float4*>(gamma + (tx << 2));
    float4 ee = *reinterpret_cast<const float4*>(beta  + (tx << 2));

    #pragma unroll
    for (int i = 0; i < 8; i++) {
        int row = base + ty * 8 + i;
        float v0, v1, v2, v3;
        unpack2(acc[i][0], v0, v1);
        unpack2(acc[i][1], v2, v3);
        v0 += bb.x; v1 += bb.y; v2 += bb.z; v3 += bb.w;
        float s1 = v0 + v1 + v2 + v3;
        float s2 = v0 * v0 + v1 * v1 + v2 * v2 + v3 * v3;
        #pragma unroll
        for (int o = 16; o > 0; o >>= 1) {
            s1 += __shfl_xor_sync(0xffffffffu, s1, o);
            s2 += __shfl_xor_sync(0xffffffffu, s2, o);
        }
        float mu = s1 * (1.0f / 128.0f);
        float var = s2 * (1.0f / 128.0f) - mu * mu;
        float rstd = rsqrtf(var + EPS_LN);
        if (row < n) {
            float4 o4;
            o4.x = fmaxf((v0 - mu) * rstd * gg.x + ee.x, 0.f);
            o4.y = fmaxf((v1 - mu) * rstd * gg.y + ee.y, 0.f);
            o4.z = fmaxf((v2 - mu) * rstd * gg.z + ee.z, 0.f);
            o4.w = fmaxf((v3 - mu) * rstd * gg.w + ee.w, 0.f);
            *reinterpret_cast<float4*>(out + (size_t)row * 128 + (tx << 2)) = o4;
        }
    }
}

// ---------------- layer-2 GEMM: t2 = h1 @ [Wr2 | Wn2]  (K=128, BN=128) -----
__global__ void __launch_bounds__(256) k_gemm2(
    const float* __restrict__ X,
    const float* __restrict__ Wr2, const float* __restrict__ Wn2,
    float* __restrict__ out, int n)
{
    __shared__ float2 As2[16][64];
    __shared__ float  Bs[16][128];

    int tid = threadIdx.x;
    int tx = tid & 31, ty = tid >> 5;
    int base = blockIdx.x * 64;

    int ar  = tid >> 2;
    int ac4 = (tid & 3) << 2;
    int arow = base + ar;
    bool arok = arow < n;

    int kb = tid >> 4;
    int jb = (tid & 15) << 3;

    u64 acc[8][2];
    #pragma unroll
    for (int i = 0; i < 8; i++) { acc[i][0] = 0ull; acc[i][1] = 0ull; }

    #pragma unroll 1
    for (int kt = 0; kt < 8; kt++) {
        int ko = kt << 4;
        float4 av = make_float4(0.f, 0.f, 0.f, 0.f);
        if (arok)
            av = *reinterpret_cast<const float4*>(X + (size_t)arow * 128 + ko + ac4);
        int kg = ko + kb;
        const float* Wp = (jb < 64) ? (Wr2 + (size_t)kg * 64 + jb)
                                    : (Wn2 + (size_t)kg * 64 + (jb - 64));
        float4 bv0 = *reinterpret_cast<const float4*>(Wp);
        float4 bv1 = *reinterpret_cast<const float4*>(Wp + 4);

        __syncthreads();
        As2[ac4 + 0][ar] = make_float2(av.x, av.x);
        As2[ac4 + 1][ar] = make_float2(av.y, av.y);
        As2[ac4 + 2][ar] = make_float2(av.z, av.z);
        As2[ac4 + 3][ar] = make_float2(av.w, av.w);
        *reinterpret_cast<float4*>(&Bs[kb][jb])     = bv0;
        *reinterpret_cast<float4*>(&Bs[kb][jb + 4]) = bv1;
        __syncthreads();

        #pragma unroll
        for (int kk = 0; kk < 16; kk++) {
            u64 a[8];
            #pragma unroll
            for (int i = 0; i < 8; i++)
                a[i] = *reinterpret_cast<const u64*>(&As2[kk][ty * 8 + i]);
            u64 b01 = *reinterpret_cast<const u64*>(&Bs[kk][tx * 4]);
            u64 b23 = *reinterpret_cast<const u64*>(&Bs[kk][tx * 4 + 2]);
            #pragma unroll
            for (int i = 0; i < 8; i++) {
                fma2(acc[i][0], a[i], b01);
                fma2(acc[i][1], a[i], b23);
            }
        }
    }

    #pragma unroll
    for (int i = 0; i < 8; i++) {
        int row = base + ty * 8 + i;
        if (row < n) {
            float v0, v1, v2, v3;
            unpack2(acc[i][0], v0, v1);
            unpack2(acc[i][1], v2, v3);
            float4 o4 = make_float4(v0, v1, v2, v3);
            *reinterpret_cast<float4*>(out + (size_t)row * 128 + (tx << 2)) = o4;
        }
    }
}

// ---------------- final: out = log_softmax(t2[:, :64] + agg64 + b2) --------
__global__ void __launch_bounds__(256) k_final(
    const float* __restrict__ t2, const float* __restrict__ agg,
    const float* __restrict__ b2, float* __restrict__ out, int n)
{
    int w = (blockIdx.x * 256 + threadIdx.x) >> 5;
    int lane = threadIdx.x & 31;
    if (w >= n) return;
    float va = t2[(size_t)w * 128 + lane]      + agg[(size_t)w * 64 + lane]      + __ldg(&b2[lane]);
    float vb = t2[(size_t)w * 128 + 32 + lane] + agg[(size_t)w * 64 + 32 + lane] + __ldg(&b2[32 + lane]);
    float m = fmaxf(va, vb);
    #pragma unroll
    for (int o = 16; o > 0; o >>= 1)
        m = fmaxf(m, __shfl_xor_sync(0xffffffffu, m, o));
    float se = expf(va - m) + expf(vb - m);
    #pragma unroll
    for (int o = 16; o > 0; o >>= 1)
        se += __shfl_xor_sync(0xffffffffu, se, o);
    float ls = m + logf(se);
    out[(size_t)w * 64 + lane]      = va - ls;
    out[(size_t)w * 64 + 32 + lane] = vb - ls;
}

// ---------------- launcher --------------------------------------------------
extern "C" void kernel_launch(void* const* d_in, const int* in_sizes, int n_in,
                              void* d_out, int out_size)
{
    const float* x   = (const float*)d_in[0];
    const int*  esrc = (const int*)d_in[1];
    const int*  edst = (const int*)d_in[2];
    const float* Wr0 = (const float*)d_in[3];
    const float* Wn0 = (const float*)d_in[4];
    const float* b0  = (const float*)d_in[5];
    const float* g0  = (const float*)d_in[6];
    const float* be0 = (const float*)d_in[7];
    const float* Wr1 = (const float*)d_in[8];
    const float* Wn1 = (const float*)d_in[9];
    const float* b1  = (const float*)d_in[10];
    const float* g1  = (const float*)d_in[11];
    const float* be1 = (const float*)d_in[12];
    const float* Wr2 = (const float*)d_in[13];
    const float* Wn2 = (const float*)d_in[14];
    const float* b2  = (const float*)d_in[15];
    float* out = (float*)d_out;

    int n = in_sizes[0] / 128;
    int E = in_sizes[1];
    if (n > MAXN) n = MAXN;
    if (E > MAXE) E = MAXE;

    int *degi, *off, *cursor, *csr;
    float *rdeg, *agg, *hA, *hB;
    cudaGetSymbolAddress((void**)&degi,   g_degi);
    cudaGetSymbolAddress((void**)&off,    g_off);
    cudaGetSymbolAddress((void**)&cursor, g_cursor);
    cudaGetSymbolAddress((void**)&csr,    g_csr);
    cudaGetSymbolAddress((void**)&rdeg,   g_rdeg);
    cudaGetSymbolAddress((void**)&agg,    g_agg);
    cudaGetSymbolAddress((void**)&hA,     g_hA);
    cudaGetSymbolAddress((void**)&hB,     g_hB);

    int gb = (n + 63) / 64;
    int gw = (n + 7) / 8;           // warp-per-node grids

    // CSR build (edge list identical across layers; rebuilt every call)
    k_zeroi<<<(n + 255) / 256, 256>>>(degi, n);
    k_count<<<(E + 255) / 256, 256>>>(edst, degi, E);
    k_scan<<<1, 1024>>>(degi, off, cursor, rdeg, n);
    k_fill<<<(E + 255) / 256, 256>>>(esrc, edst, cursor, csr, E);

    // layer 0
    k_agg128<<<gw, 256>>>(x, csr, off, rdeg, agg, n);
    k_gemm_ln<<<gb, 256>>>(x, agg, Wr0, Wn0, b0, g0, be0, hA, n);

    // layer 1
    k_agg128<<<gw, 256>>>(hA, csr, off, rdeg, agg, n);
    k_gemm_ln<<<gb, 256>>>(hA, agg, Wr1, Wn1, b1, g1, be1, hB, n);

    // layer 2: t2 = h1 @ [Wr2 | Wn2]; aggregate the Wn half post-GEMM (64-wide)
    k_gemm2<<<gb, 256>>>(hB, Wr2, Wn2, hA, n);
    k_agg64<<<gw, 256>>>(hA, csr, off, rdeg, agg, n);
    k_final<<<gw, 256>>>(hA, agg, b2, out, n);
}

// round 3
// speedup vs baseline: 1.2094x; 1.0742x over previous
#include <cuda_runtime.h>
#include <cstdint>

#define MAXN 100000
#define MAXE 1600000
#define EPS_LN 1e-5f

// ---------------- scratch (device globals; no allocation allowed) ----------
__device__ int   g_degi[MAXN];
__device__ int   g_off[MAXN + 1];
__device__ int   g_cursor[MAXN];
__device__ int   g_csr[MAXE];                     // src ids grouped by dst
__device__ float g_rdeg[MAXN];                    // 1/max(deg,1)
__device__ float g_agg[(size_t)MAXN * 128];       // mean-agg result
__device__ float g_hA[(size_t)MAXN * 128];        // h0, then t2
__device__ float g_hB[(size_t)MAXN * 128];        // h1

typedef unsigned long long u64;
typedef unsigned int u32;

// ---------------- packed fp32x2 helpers (Blackwell FFMA2 pipe) -------------
__device__ __forceinline__ void unpack2(u64 v, float& a, float& b) {
    u32 lo, hi;
    asm("mov.b64 {%0, %1}, %2;" : "=r"(lo), "=r"(hi) : "l"(v));
    a = __uint_as_float(lo); b = __uint_as_float(hi);
}
__device__ __forceinline__ u64 dup2(float f) {
    u64 r;
    asm("mov.b64 %0, {%1, %1};" : "=l"(r) : "r"(__float_as_uint(f)));
    return r;
}
__device__ __forceinline__ void fma2(u64& d, u64 a, u64 b) {
    asm("fma.rn.f32x2 %0, %1, %2, %0;" : "+l"(d) : "l"(a), "l"(b));
}

// ---------------- CSR build --------------------------------------------------
__global__ void k_zeroi(int* __restrict__ p, int n) {
    int i = blockIdx.x * blockDim.x + threadIdx.x;
    if (i < n) p[i] = 0;
}

__global__ void k_count(const int* __restrict__ dst, int* __restrict__ deg, int E) {
    int i = blockIdx.x * blockDim.x + threadIdx.x;
    if (i < E) atomicAdd(&deg[dst[i]], 1);
}

// single-block exclusive scan over deg -> off/cursor, plus rdeg
__global__ void __launch_bounds__(1024) k_scan(
    const int* __restrict__ deg, int* __restrict__ off,
    int* __restrict__ cursor, float* __restrict__ rdeg, int n)
{
    __shared__ int sb[1024];
    int tid = threadIdx.x;
    int chunk = (n + 1023) >> 10;
    int s = tid * chunk;
    int e = min(s + chunk, n);
    int sum = 0;
    for (int i = s; i < e; i++) sum += deg[i];
    sb[tid] = sum;
    __syncthreads();
    int val = sum;
    for (int o = 1; o < 1024; o <<= 1) {
        int t = (tid >= o) ? sb[tid - o] : 0;
        __syncthreads();
        sb[tid] += t;
        __syncthreads();
    }
    int base = sb[tid] - val;   // exclusive prefix
    for (int i = s; i < e; i++) {
        int d = deg[i];
        off[i] = base;
        cursor[i] = base;
        rdeg[i] = 1.0f / fmaxf((float)d, 1.0f);
        base += d;
    }
    if (tid == 1023) off[n] = base;
}

__global__ void k_fill(const int* __restrict__ src, const int* __restrict__ dst,
                       int* __restrict__ cursor, int* __restrict__ csr, int E)
{
    int i = blockIdx.x * blockDim.x + threadIdx.x;
    if (i < E) {
        int p = atomicAdd(&cursor[dst[i]], 1);
        csr[p] = src[i];
    }
}

// ---------------- gather-based mean aggregation (no atomics) ---------------
// one warp per dst node; each lane owns 4 cols; 4-deep unroll for MLP
__global__ void __launch_bounds__(256) k_agg128(
    const float* __restrict__ feat, const int* __restrict__ csr,
    const int* __restrict__ off, const float* __restrict__ rdeg,
    float* __restrict__ agg, int n)
{
    int w = (blockIdx.x * 256 + threadIdx.x) >> 5;
    int lane = threadIdx.x & 31;
    if (w >= n) return;
    int s0 = off[w], s1 = off[w + 1];
    float4 a0 = make_float4(0.f, 0.f, 0.f, 0.f);
    float4 a1 = make_float4(0.f, 0.f, 0.f, 0.f);
    float4 a2 = make_float4(0.f, 0.f, 0.f, 0.f);
    float4 a3 = make_float4(0.f, 0.f, 0.f, 0.f);
    int e = s0;
    for (; e + 4 <= s1; e += 4) {
        int i0 = csr[e], i1 = csr[e + 1], i2 = csr[e + 2], i3 = csr[e + 3];
        float4 v0 = *reinterpret_cast<const float4*>(feat + (size_t)i0 * 128 + lane * 4);
        float4 v1 = *reinterpret_cast<const float4*>(feat + (size_t)i1 * 128 + lane * 4);
        float4 v2 = *reinterpret_cast<const float4*>(feat + (size_t)i2 * 128 + lane * 4);
        float4 v3 = *reinterpret_cast<const float4*>(feat + (size_t)i3 * 128 + lane * 4);
        a0.x += v0.x; a0.y += v0.y; a0.z += v0.z; a0.w += v0.w;
        a1.x += v1.x; a1.y += v1.y; a1.z += v1.z; a1.w += v1.w;
        a2.x += v2.x; a2.y += v2.y; a2.z += v2.z; a2.w += v2.w;
        a3.x += v3.x; a3.y += v3.y; a3.z += v3.z; a3.w += v3.w;
    }
    for (; e < s1; e++) {
        int i0 = csr[e];
        float4 v0 = *reinterpret_cast<const float4*>(feat + (size_t)i0 * 128 + lane * 4);
        a0.x += v0.x; a0.y += v0.y; a0.z += v0.z; a0.w += v0.w;
    }
    float r = rdeg[w];
    float4 o4;
    o4.x = ((a0.x + a1.x) + (a2.x + a3.x)) * r;
    o4.y = ((a0.y + a1.y) + (a2.y + a3.y)) * r;
    o4.z = ((a0.z + a1.z) + (a2.z + a3.z)) * r;
    o4.w = ((a0.w + a1.w) + (a2.w + a3.w)) * r;
    *reinterpret_cast<float4*>(agg + (size_t)w * 128 + lane * 4) = o4;
}

// cols [64,128) of t2 -> 64-wide mean agg; half-warp per edge stream
__global__ void __launch_bounds__(256) k_agg64(
    const float* __restrict__ t2, const int* __restrict__ csr,
    const int* __restrict__ off, const float* __restrict__ rdeg,
    float* __restrict__ agg, int n)
{
    int w = (blockIdx.x * 256 + threadIdx.x) >> 5;
    int lane = threadIdx.x & 31;
    if (w >= n) return;
    int half = lane >> 4, l = lane & 15;
    int s0 = off[w], s1 = off[w + 1];
    float4 a = make_float4(0.f, 0.f, 0.f, 0.f);
    float4 b = make_float4(0.f, 0.f, 0.f, 0.f);
    int e = s0 + half;
    for (; e + 2 < s1; e += 4) {
        int i0 = csr[e], i1 = csr[e + 2];
        float4 v0 = *reinterpret_cast<const float4*>(t2 + (size_t)i0 * 128 + 64 + l * 4);
        float4 v1 = *reinterpret_cast<const float4*>(t2 + (size_t)i1 * 128 + 64 + l * 4);
        a.x += v0.x; a.y += v0.y; a.z += v0.z; a.w += v0.w;
        b.x += v1.x; b.y += v1.y; b.z += v1.z; b.w += v1.w;
    }
    if (e < s1) {
        int i0 = csr[e];
        float4 v0 = *reinterpret_cast<const float4*>(t2 + (size_t)i0 * 128 + 64 + l * 4);
        a.x += v0.x; a.y += v0.y; a.z += v0.z; a.w += v0.w;
    }
    a.x += b.x; a.y += b.y; a.z += b.z; a.w += b.w;
    a.x += __shfl_xor_sync(0xffffffffu, a.x, 16);
    a.y += __shfl_xor_sync(0xffffffffu, a.y, 16);
    a.z += __shfl_xor_sync(0xffffffffu, a.z, 16);
    a.w += __shfl_xor_sync(0xffffffffu, a.w, 16);
    if (half == 0) {
        float r = rdeg[w];
        float4 o4 = make_float4(a.x * r, a.y * r, a.z * r, a.w * r);
        *reinterpret_cast<float4*>(agg + (size_t)w * 64 + l * 4) = o4;
    }
}

// ---------------- fused GEMM (K=256: [x | agg]) + bias + LN + ReLU ---------
// BM=128, BN=128, BK=16, 256 threads, thread tile 8x8 (f32x2 accumulators).
__global__ void __launch_bounds__(256) k_gemm_ln(
    const float* __restrict__ X, const float* __restrict__ AGG,
    const float* __restrict__ Wr, const float* __restrict__ Wn,
    const float* __restrict__ bias, const float* __restrict__ gamma,
    const float* __restrict__ beta,
    float* __restrict__ out, int n)
{
    __shared__ float As[16][128];
    __shared__ float Bs[16][128];

    int tid = threadIdx.x;
    int ty = tid >> 4;              // 0..15 -> rows ty*8..+8
    int tx = tid & 15;              // 0..15 -> cols tx*8..+8
    int base = blockIdx.x * 128;

    // loader mapping
    int lrow = tid >> 1;            // 0..127
    int lk   = (tid & 1) << 3;      // 0 or 8
    int arow = base + lrow;
    bool arok = arow < n;
    int kb = tid >> 4;              // 0..15 (B k within tile)
    int jb = (tid & 15) << 3;       // 0..120 (B col)

    u64 acc[8][4];
    #pragma unroll
    for (int i = 0; i < 8; i++)
        #pragma unroll
        for (int j = 0; j < 4; j++) acc[i][j] = 0ull;

    #pragma unroll 1
    for (int kt = 0; kt < 16; kt++) {
        int ko = kt << 4;
        float4 av0 = make_float4(0.f, 0.f, 0.f, 0.f);
        float4 av1 = make_float4(0.f, 0.f, 0.f, 0.f);
        if (arok) {
            int kg = ko + lk;
            const float* P = (kg < 128) ? (X + (size_t)arow * 128 + kg)
                                        : (AGG + (size_t)arow * 128 + (kg - 128));
            av0 = *reinterpret_cast<const float4*>(P);
            av1 = *reinterpret_cast<const float4*>(P + 4);
        }
        int kgb = ko + kb;
        const float* Wp = (kgb < 128) ? (Wr + (size_t)kgb * 128)
                                      : (Wn + (size_t)(kgb - 128) * 128);
        float4 bv0 = *reinterpret_cast<const float4*>(Wp + jb);
        float4 bv1 = *reinterpret_cast<const float4*>(Wp + jb + 4);

        __syncthreads();
        As[lk + 0][lrow] = av0.x;
        As[lk + 1][lrow] = av0.y;
        As[lk + 2][lrow] = av0.z;
        As[lk + 3][lrow] = av0.w;
        As[lk + 4][lrow] = av1.x;
        As[lk + 5][lrow] = av1.y;
        As[lk + 6][lrow] = av1.z;
        As[lk + 7][lrow] = av1.w;
        *reinterpret_cast<float4*>(&Bs[kb][jb])     = bv0;
        *reinterpret_cast<float4*>(&Bs[kb][jb + 4]) = bv1;
        __syncthreads();

        #pragma unroll
        for (int kk = 0; kk < 16; kk++) {
            float4 a0 = *reinterpret_cast<const float4*>(&As[kk][ty * 8]);
            float4 a1 = *reinterpret_cast<const float4*>(&As[kk][ty * 8 + 4]);
            u64 b0 = *reinterpret_cast<const u64*>(&Bs[kk][tx * 8]);
            u64 b1 = *reinterpret_cast<const u64*>(&Bs[kk][tx * 8 + 2]);
            u64 b2 = *reinterpret_cast<const u64*>(&Bs[kk][tx * 8 + 4]);
            u64 b3 = *reinterpret_cast<const u64*>(&Bs[kk][tx * 8 + 6]);
            u64 ad;
            ad = dup2(a0.x); fma2(acc[0][0], ad, b0); fma2(acc[0][1], ad, b1); fma2(acc[0][2], ad, b2); fma2(acc[0][3], ad, b3);
            ad = dup2(a0.y); fma2(acc[1][0], ad, b0); fma2(acc[1][1], ad, b1); fma2(acc[1][2], ad, b2); fma2(acc[1][3], ad, b3);
            ad = dup2(a0.z); fma2(acc[2][0], ad, b0); fma2(acc[2][1], ad, b1); fma2(acc[2][2], ad, b2); fma2(acc[2][3], ad, b3);
            ad = dup2(a0.w); fma2(acc[3][0], ad, b0); fma2(acc[3][1], ad, b1); fma2(acc[3][2], ad, b2); fma2(acc[3][3], ad, b3);
            ad = dup2(a1.x); fma2(acc[4][0], ad, b0); fma2(acc[4][1], ad, b1); fma2(acc[4][2], ad, b2); fma2(acc[4][3], ad, b3);
            ad = dup2(a1.y); fma2(acc[5][0], ad, b0); fma2(acc[5][1], ad, b1); fma2(acc[5][2], ad, b2); fma2(acc[5][3], ad, b3);
            ad = dup2(a1.z); fma2(acc[6][0], ad, b0); fma2(acc[6][1], ad, b1); fma2(acc[6][2], ad, b2); fma2(acc[6][3], ad, b3);
            ad = dup2(a1.w); fma2(acc[7][0], ad, b0); fma2(acc[7][1], ad, b1); fma2(acc[7][2], ad, b2); fma2(acc[7][3], ad, b3);
        }
    }

    // epilogue: +bias, LayerNorm across 128 cols (16-lane groups share a row), ReLU
    int col0 = tx << 3;
    float4 bb0 = *reinterpret_cast<const float4*>(bias  + col0);
    float4 bb1 = *reinterpret_cast<const float4*>(bias  + col0 + 4);
    float4 gg0 = *reinterpret_cast<const float4*>(gamma + col0);
    float4 gg1 = *reinterpret_cast<const float4*>(gamma + col0 + 4);
    float4 ee0 = *reinterpret_cast<const float4*>(beta  + col0);
    float4 ee1 = *reinterpret_cast<const float4*>(beta  + col0 + 4);

    #pragma unroll
    for (int i = 0; i < 8; i++) {
        int row = base + ty * 8 + i;
        float v[8];
        unpack2(acc[i][0], v[0], v[1]);
        unpack2(acc[i][1], v[2], v[3]);
        unpack2(acc[i][2], v[4], v[5]);
        unpack2(acc[i][3], v[6], v[7]);
        v[0] += bb0.x; v[1] += bb0.y; v[2] += bb0.z; v[3] += bb0.w;
        v[4] += bb1.x; v[5] += bb1.y; v[6] += bb1.z; v[7] += bb1.w;
        float s1 = 0.f, s2 = 0.f;
        #pragma unroll
        for (int c = 0; c < 8; c++) { s1 += v[c]; s2 += v[c] * v[c]; }
        #pragma unroll
        for (int o = 8; o > 0; o >>= 1) {
            s1 += __shfl_xor_sync(0xffffffffu, s1, o);
            s2 += __shfl_xor_sync(0xffffffffu, s2, o);
        }
        float mu = s1 * (1.0f / 128.0f);
        float var = s2 * (1.0f / 128.0f) - mu * mu;
        float rstd = rsqrtf(var + EPS_LN);
        if (row < n) {
            float4 o0, o1;
            o0.x = fmaxf((v[0] - mu) * rstd * gg0.x + ee0.x, 0.f);
            o0.y = fmaxf((v[1] - mu) * rstd * gg0.y + ee0.y, 0.f);
            o0.z = fmaxf((v[2] - mu) * rstd * gg0.z + ee0.z, 0.f);
            o0.w = fmaxf((v[3] - mu) * rstd * gg0.w + ee0.w, 0.f);
            o1.x = fmaxf((v[4] - mu) * rstd * gg1.x + ee1.x, 0.f);
            o1.y = fmaxf((v[5] - mu) * rstd * gg1.y + ee1.y, 0.f);
            o1.z = fmaxf((v[6] - mu) * rstd * gg1.z + ee1.z, 0.f);
            o1.w = fmaxf((v[7] - mu) * rstd * gg1.w + ee1.w, 0.f);
            *reinterpret_cast<float4*>(out + (size_t)row * 128 + col0)     = o0;
            *reinterpret_cast<float4*>(out + (size_t)row * 128 + col0 + 4) = o1;
        }
    }
}

// ---------------- layer-2 GEMM: t2 = h1 @ [Wr2 | Wn2]  (K=128, BN=128) -----
__global__ void __launch_bounds__(256) k_gemm2(
    const float* __restrict__ X,
    const float* __restrict__ Wr2, const float* __restrict__ Wn2,
    float* __restrict__ out, int n)
{
    __shared__ float As[16][128];
    __shared__ float Bs[16][128];

    int tid = threadIdx.x;
    int ty = tid >> 4;
    int tx = tid & 15;
    int base = blockIdx.x * 128;

    int lrow = tid >> 1;
    int lk   = (tid & 1) << 3;
    int arow = base + lrow;
    bool arok = arow < n;
    int kb = tid >> 4;
    int jb = (tid & 15) << 3;

    u64 acc[8][4];
    #pragma unroll
    for (int i = 0; i < 8; i++)
        #pragma unroll
        for (int j = 0; j < 4; j++) acc[i][j] = 0ull;

    #pragma unroll 1
    for (int kt = 0; kt < 8; kt++) {
        int ko = kt << 4;
        float4 av0 = make_float4(0.f, 0.f, 0.f, 0.f);
        float4 av1 = make_float4(0.f, 0.f, 0.f, 0.f);
        if (arok) {
            const float* P = X + (size_t)arow * 128 + ko + lk;
            av0 = *reinterpret_cast<const float4*>(P);
            av1 = *reinterpret_cast<const float4*>(P + 4);
        }
        int kgb = ko + kb;
        const float* Wp = (jb < 64) ? (Wr2 + (size_t)kgb * 64 + jb)
                                    : (Wn2 + (size_t)kgb * 64 + (jb - 64));
        float4 bv0 = *reinterpret_cast<const float4*>(Wp);
        float4 bv1 = *reinterpret_cast<const float4*>(Wp + 4);

        __syncthreads();
        As[lk + 0][lrow] = av0.x;
        As[lk + 1][lrow] = av0.y;
        As[lk + 2][lrow] = av0.z;
        As[lk + 3][lrow] = av0.w;
        As[lk + 4][lrow] = av1.x;
        As[lk + 5][lrow] = av1.y;
        As[lk + 6][lrow] = av1.z;
        As[lk + 7][lrow] = av1.w;
        *reinterpret_cast<float4*>(&Bs[kb][jb])     = bv0;
        *reinterpret_cast<float4*>(&Bs[kb][jb + 4]) = bv1;
        __syncthreads();

        #pragma unroll
        for (int kk = 0; kk < 16; kk++) {
            float4 a0 = *reinterpret_cast<const float4*>(&As[kk][ty * 8]);
            float4 a1 = *reinterpret_cast<const float4*>(&As[kk][ty * 8 + 4]);
            u64 b0 = *reinterpret_cast<const u64*>(&Bs[kk][tx * 8]);
            u64 b1 = *reinterpret_cast<const u64*>(&Bs[kk][tx * 8 + 2]);
            u64 b2 = *reinterpret_cast<const u64*>(&Bs[kk][tx * 8 + 4]);
            u64 b3 = *reinterpret_cast<const u64*>(&Bs[kk][tx * 8 + 6]);
            u64 ad;
            ad = dup2(a0.x); fma2(acc[0][0], ad, b0); fma2(acc[0][1], ad, b1); fma2(acc[0][2], ad, b2); fma2(acc[0][3], ad, b3);
            ad = dup2(a0.y); fma2(acc[1][0], ad, b0); fma2(acc[1][1], ad, b1); fma2(acc[1][2], ad, b2); fma2(acc[1][3], ad, b3);
            ad = dup2(a0.z); fma2(acc[2][0], ad, b0); fma2(acc[2][1], ad, b1); fma2(acc[2][2], ad, b2); fma2(acc[2][3], ad, b3);
            ad = dup2(a0.w); fma2(acc[3][0], ad, b0); fma2(acc[3][1], ad, b1); fma2(acc[3][2], ad, b2); fma2(acc[3][3], ad, b3);
            ad = dup2(a1.x); fma2(acc[4][0], ad, b0); fma2(acc[4][1], ad, b1); fma2(acc[4][2], ad, b2); fma2(acc[4][3], ad, b3);
            ad = dup2(a1.y); fma2(acc[5][0], ad, b0); fma2(acc[5][1], ad, b1); fma2(acc[5][2], ad, b2); fma2(acc[5][3], ad, b3);
            ad = dup2(a1.z); fma2(acc[6][0], ad, b0); fma2(acc[6][1], ad, b1); fma2(acc[6][2], ad, b2); fma2(acc[6][3], ad, b3);
            ad = dup2(a1.w); fma2(acc[7][0], ad, b0); fma2(acc[7][1], ad, b1); fma2(acc[7][2], ad, b2); fma2(acc[7][3], ad, b3);
        }
    }

    int col0 = tx << 3;
    #pragma unroll
    for (int i = 0; i < 8; i++) {
        int row = base + ty * 8 + i;
        if (row < n) {
            float v[8];
            unpack2(acc[i][0], v[0], v[1]);
            unpack2(acc[i][1], v[2], v[3]);
            unpack2(acc[i][2], v[4], v[5]);
            unpack2(acc[i][3], v[6], v[7]);
            *reinterpret_cast<float4*>(out + (size_t)row * 128 + col0)     = make_float4(v[0], v[1], v[2], v[3]);
            *reinterpret_cast<float4*>(out + (size_t)row * 128 + col0 + 4) = make_float4(v[4], v[5], v[6], v[7]);
        }
    }
}

// ---------------- final: out = log_softmax(t2[:, :64] + agg64 + b2) --------
__global__ void __launch_bounds__(256) k_final(
    const float* __restrict__ t2, const float* __restrict__ agg,
    const float* __restrict__ b2, float* __restrict__ out, int n)
{
    int w = (blockIdx.x * 256 + threadIdx.x) >> 5;
    int lane = threadIdx.x & 31;
    if (w >= n) return;
    float va = t2[(size_t)w * 128 + lane]      + agg[(size_t)w * 64 + lane]      + __ldg(&b2[lane]);
    float vb = t2[(size_t)w * 128 + 32 + lane] + agg[(size_t)w * 64 + 32 + lane] + __ldg(&b2[32 + lane]);
    float m = fmaxf(va, vb);
    #pragma unroll
    for (int o = 16; o > 0; o >>= 1)
        m = fmaxf(m, __shfl_xor_sync(0xffffffffu, m, o));
    float se = expf(va - m) + expf(vb - m);
    #pragma unroll
    for (int o = 16; o > 0; o >>= 1)
        se += __shfl_xor_sync(0xffffffffu, se, o);
    float ls = m + logf(se);
    out[(size_t)w * 64 + lane]      = va - ls;
    out[(size_t)w * 64 + 32 + lane] = vb - ls;
}

// ---------------- launcher --------------------------------------------------
extern "C" void kernel_launch(void* const* d_in, const int* in_sizes, int n_in,
                              void* d_out, int out_size)
{
    const float* x   = (const float*)d_in[0];
    const int*  esrc = (const int*)d_in[1];
    const int*  edst = (const int*)d_in[2];
    const float* Wr0 = (const float*)d_in[3];
    const float* Wn0 = (const float*)d_in[4];
    const float* b0  = (const float*)d_in[5];
    const float* g0  = (const float*)d_in[6];
    const float* be0 = (const float*)d_in[7];
    const float* Wr1 = (const float*)d_in[8];
    const float* Wn1 = (const float*)d_in[9];
    const float* b1  = (const float*)d_in[10];
    const float* g1  = (const float*)d_in[11];
    const float* be1 = (const float*)d_in[12];
    const float* Wr2 = (const float*)d_in[13];
    const float* Wn2 = (const float*)d_in[14];
    const float* b2  = (const float*)d_in[15];
    float* out = (float*)d_out;

    int n = in_sizes[0] / 128;
    int E = in_sizes[1];
    if (n > MAXN) n = MAXN;
    if (E > MAXE) E = MAXE;

    int *degi, *off, *cursor, *csr;
    float *rdeg, *agg, *hA, *hB;
    cudaGetSymbolAddress((void**)&degi,   g_degi);
    cudaGetSymbolAddress((void**)&off,    g_off);
    cudaGetSymbolAddress((void**)&cursor, g_cursor);
    cudaGetSymbolAddress((void**)&csr,    g_csr);
    cudaGetSymbolAddress((void**)&rdeg,   g_rdeg);
    cudaGetSymbolAddress((void**)&agg,    g_agg);
    cudaGetSymbolAddress((void**)&hA,     g_hA);
    cudaGetSymbolAddress((void**)&hB,     g_hB);

    int gb = (n + 127) / 128;
    int gw = (n + 7) / 8;           // warp-per-node grids

    // CSR build (edge list identical across layers; rebuilt every call)
    k_zeroi<<<(n + 255) / 256, 256>>>(degi, n);
    k_count<<<(E + 255) / 256, 256>>>(edst, degi, E);
    k_scan<<<1, 1024>>>(degi, off, cursor, rdeg, n);
    k_fill<<<(E + 255) / 256, 256>>>(esrc, edst, cursor, csr, E);

    // layer 0
    k_agg128<<<gw, 256>>>(x, csr, off, rdeg, agg, n);
    k_gemm_ln<<<gb, 256>>>(x, agg, Wr0, Wn0, b0, g0, be0, hA, n);

    // layer 1
    k_agg128<<<gw, 256>>>(hA, csr, off, rdeg, agg, n);
    k_gemm_ln<<<gb, 256>>>(hA, agg, Wr1, Wn1, b1, g1, be1, hB, n);

    // layer 2: t2 = h1 @ [Wr2 | Wn2]; aggregate the Wn half post-GEMM (64-wide)
    k_gemm2<<<gb, 256>>>(hB, Wr2, Wn2, hA, n);
    k_agg64<<<gw, 256>>>(hA, csr, off, rdeg, agg, n);
    k_final<<<gw, 256>>>(hA, agg, b2, out, n);
}

// round 5
// speedup vs baseline: 1.7502x; 1.4471x over previous
#include <cuda_runtime.h>
#include <cstdint>

#define MAXN 100000
#define MAXE 1600000
#define EPS_LN 1e-5f

typedef unsigned long long u64;
typedef unsigned int u32;

// ---------------- scratch (device globals; no allocation allowed) ----------
__device__ int   g_degi[MAXN];
__device__ int   g_off[MAXN + 1];
__device__ int   g_cursor[MAXN];
__device__ int   g_csr[MAXE];
__device__ float g_rdeg[MAXN];
__device__ float g_agg[(size_t)MAXN * 128];
__device__ float g_hA[(size_t)MAXN * 128];
__device__ float g_hB[(size_t)MAXN * 128];
__device__ float g_Bw0[256 * 128];   // [k][n] tf32-rounded concat weights
__device__ float g_Bw1[256 * 128];
__device__ float g_Bw2[128 * 128];

// ---------------- helpers ---------------------------------------------------
__device__ __forceinline__ float tf32r(float f) {
    uint32_t u;
    asm("cvt.rna.tf32.f32 %0, %1;" : "=r"(u) : "f"(f));
    return __uint_as_float(u);
}
__device__ __forceinline__ uint32_t smem_u32(const void* p) {
    uint32_t a;
    asm("{ .reg .u64 t; cvta.to.shared.u64 t, %1; cvt.u32.u64 %0, t; }" : "=r"(a) : "l"(p));
    return a;
}
__device__ __forceinline__ void cp_async16(uint32_t dst, const void* src) {
    asm volatile("cp.async.ca.shared.global [%0], [%1], 16;" :: "r"(dst), "l"(src));
}
__device__ __forceinline__ void cp_commit() {
    asm volatile("cp.async.commit_group;" ::: "memory");
}
__device__ __forceinline__ void cp_wait0() {
    asm volatile("cp.async.wait_group 0;" ::: "memory");
}
__device__ __forceinline__ void mma_tf32(float* c, const u32* a, const u32* b) {
    asm volatile(
        "mma.sync.aligned.m16n8k8.row.col.f32.tf32.tf32.f32 "
        "{%0,%1,%2,%3}, {%4,%5,%6,%7}, {%8,%9}, {%0,%1,%2,%3};"
        : "+f"(c[0]), "+f"(c[1]), "+f"(c[2]), "+f"(c[3])
        : "r"(a[0]), "r"(a[1]), "r"(a[2]), "r"(a[3]), "r"(b[0]), "r"(b[1]));
}

// ---------------- CSR build --------------------------------------------------
__global__ void k_zeroi(int* __restrict__ p, int n) {
    int i = blockIdx.x * blockDim.x + threadIdx.x;
    if (i < n) p[i] = 0;
}

__global__ void k_count(const int* __restrict__ dst, int* __restrict__ deg, int E) {
    int i = blockIdx.x * blockDim.x + threadIdx.x;
    if (i < E) atomicAdd(&deg[dst[i]], 1);
}

__global__ void __launch_bounds__(1024) k_scan(
    const int* __restrict__ deg, int* __restrict__ off,
    int* __restrict__ cursor, float* __restrict__ rdeg, int n)
{
    __shared__ int sb[1024];
    int tid = threadIdx.x;
    int chunk = (n + 1023) >> 10;
    int s = tid * chunk;
    int e = min(s + chunk, n);
    int sum = 0;
    for (int i = s; i < e; i++) sum += deg[i];
    sb[tid] = sum;
    __syncthreads();
    int val = sum;
    for (int o = 1; o < 1024; o <<= 1) {
        int t = (tid >= o) ? sb[tid - o] : 0;
        __syncthreads();
        sb[tid] += t;
        __syncthreads();
    }
    int base = sb[tid] - val;
    for (int i = s; i < e; i++) {
        int d = deg[i];
        off[i] = base;
        cursor[i] = base;
        rdeg[i] = 1.0f / fmaxf((float)d, 1.0f);
        base += d;
    }
    if (tid == 1023) off[n] = base;
}

__global__ void k_fill(const int* __restrict__ src, const int* __restrict__ dst,
                       int* __restrict__ cursor, int* __restrict__ csr, int E)
{
    int i = blockIdx.x * blockDim.x + threadIdx.x;
    if (i < E) {
        int p = atomicAdd(&cursor[dst[i]], 1);
        csr[p] = src[i];
    }
}

// ---------------- weight prep (tf32 round, concat, [k][n]) -----------------
__global__ void k_prep01(const float* __restrict__ Wr, const float* __restrict__ Wn,
                         float* __restrict__ Bw)
{
    int i = blockIdx.x * blockDim.x + threadIdx.x;
    if (i < 256 * 128) {
        int k = i >> 7, nn = i & 127;
        float v = (k < 128) ? Wr[k * 128 + nn] : Wn[(k - 128) * 128 + nn];
        Bw[i] = tf32r(v);
    }
}

__global__ void k_prep2(const float* __restrict__ Wr2, const float* __restrict__ Wn2,
                        float* __restrict__ Bw)
{
    int i = blockIdx.x * blockDim.x + threadIdx.x;
    if (i < 128 * 128) {
        int k = i >> 7, nn = i & 127;
        float v = (nn < 64) ? Wr2[k * 64 + nn] : Wn2[k * 64 + (nn - 64)];
        Bw[i] = tf32r(v);
    }
}

// ---------------- gather-based mean aggregation ----------------------------
__global__ void __launch_bounds__(256) k_agg128(
    const float* __restrict__ feat, const int* __restrict__ csr,
    const int* __restrict__ off, const float* __restrict__ rdeg,
    float* __restrict__ agg, int n)
{
    int w = (blockIdx.x * 256 + threadIdx.x) >> 5;
    int lane = threadIdx.x & 31;
    if (w >= n) return;
    int s0 = off[w], s1 = off[w + 1];
    float4 a0 = make_float4(0.f, 0.f, 0.f, 0.f);
    float4 a1 = make_float4(0.f, 0.f, 0.f, 0.f);
    float4 a2 = make_float4(0.f, 0.f, 0.f, 0.f);
    float4 a3 = make_float4(0.f, 0.f, 0.f, 0.f);
    int e = s0;
    for (; e + 4 <= s1; e += 4) {
        int i0 = csr[e], i1 = csr[e + 1], i2 = csr[e + 2], i3 = csr[e + 3];
        float4 v0 = *reinterpret_cast<const float4*>(feat + (size_t)i0 * 128 + lane * 4);
        float4 v1 = *reinterpret_cast<const float4*>(feat + (size_t)i1 * 128 + lane * 4);
        float4 v2 = *reinterpret_cast<const float4*>(feat + (size_t)i2 * 128 + lane * 4);
        float4 v3 = *reinterpret_cast<const float4*>(feat + (size_t)i3 * 128 + lane * 4);
        a0.x += v0.x; a0.y += v0.y; a0.z += v0.z; a0.w += v0.w;
        a1.x += v1.x; a1.y += v1.y; a1.z += v1.z; a1.w += v1.w;
        a2.x += v2.x; a2.y += v2.y; a2.z += v2.z; a2.w += v2.w;
        a3.x += v3.x; a3.y += v3.y; a3.z += v3.z; a3.w += v3.w;
    }
    for (; e < s1; e++) {
        int i0 = csr[e];
        float4 v0 = *reinterpret_cast<const float4*>(feat + (size_t)i0 * 128 + lane * 4);
        a0.x += v0.x; a0.y += v0.y; a0.z += v0.z; a0.w += v0.w;
    }
    float r = rdeg[w];
    float4 o4;
    o4.x = ((a0.x + a1.x) + (a2.x + a3.x)) * r;
    o4.y = ((a0.y + a1.y) + (a2.y + a3.y)) * r;
    o4.z = ((a0.z + a1.z) + (a2.z + a3.z)) * r;
    o4.w = ((a0.w + a1.w) + (a2.w + a3.w)) * r;
    *reinterpret_cast<float4*>(agg + (size_t)w * 128 + lane * 4) = o4;
}

__global__ void __launch_bounds__(256) k_agg64(
    const float* __restrict__ t2, const int* __restrict__ csr,
    const int* __restrict__ off, const float* __restrict__ rdeg,
    float* __restrict__ agg, int n)
{
    int w = (blockIdx.x * 256 + threadIdx.x) >> 5;
    int lane = threadIdx.x & 31;
    if (w >= n) return;
    int half = lane >> 4, l = lane & 15;
    int s0 = off[w], s1 = off[w + 1];
    float4 a = make_float4(0.f, 0.f, 0.f, 0.f);
    float4 b = make_float4(0.f, 0.f, 0.f, 0.f);
    int e = s0 + half;
    for (; e + 2 < s1; e += 4) {
        int i0 = csr[e], i1 = csr[e + 2];
        float4 v0 = *reinterpret_cast<const float4*>(t2 + (size_t)i0 * 128 + 64 + l * 4);
        float4 v1 = *reinterpret_cast<const float4*>(t2 + (size_t)i1 * 128 + 64 + l * 4);
        a.x += v0.x; a.y += v0.y; a.z += v0.z; a.w += v0.w;
        b.x += v1.x; b.y += v1.y; b.z += v1.z; b.w += v1.w;
    }
    if (e < s1) {
        int i0 = csr[e];
        float4 v0 = *reinterpret_cast<const float4*>(t2 + (size_t)i0 * 128 + 64 + l * 4);
        a.x += v0.x; a.y += v0.y; a.z += v0.z; a.w += v0.w;
    }
    a.x += b.x; a.y += b.y; a.z += b.z; a.w += b.w;
    a.x += __shfl_xor_sync(0xffffffffu, a.x, 16);
    a.y += __shfl_xor_sync(0xffffffffu, a.y, 16);
    a.z += __shfl_xor_sync(0xffffffffu, a.z, 16);
    a.w += __shfl_xor_sync(0xffffffffu, a.w, 16);
    if (half == 0) {
        float r = rdeg[w];
        float4 o4 = make_float4(a.x * r, a.y * r, a.z * r, a.w * r);
        *reinterpret_cast<float4*>(agg + (size_t)w * 64 + l * 4) = o4;
    }
}

// ---------------- tf32 mma.sync GEMM + fused bias/LN/ReLU ------------------
// CTA tile 128x128, 8 warps (4 in M x 2 in N), warp tile 32x64, BK=32.
// A = [X | AGG] (KTOT=256) or X (KTOT=128). B = Bw [k][n] (tf32-rounded).
// smem bytes: As 2x18432 @0 | Bs 2x17408 @36864 | LN vecs @71680 | srow overlays @0
#define S_AS0 0
#define S_AS1 18432
#define S_BS0 36864
#define S_BS1 54272
#define S_BIAS 71680
#define S_GAM  72192
#define S_BET  72704
#define S_MU   73216
#define S_RS   73728
#define S_TOTAL 74240

template<int KTOT, bool DO_LN>
__global__ void __launch_bounds__(256) k_gemm_mma(
    const float* __restrict__ X, const float* __restrict__ AGG,
    const float* __restrict__ Bw, const float* __restrict__ bias,
    const float* __restrict__ gamma, const float* __restrict__ beta,
    float* __restrict__ out, int n)
{
    constexpr int NC = KTOT / 32;
    extern __shared__ char sm[];
    float* sbias = (float*)(sm + S_BIAS);
    float* sgam  = (float*)(sm + S_GAM);
    float* sbet  = (float*)(sm + S_BET);
    float* smu   = (float*)(sm + S_MU);
    float* srs   = (float*)(sm + S_RS);
    float* srow  = (float*)(sm + 0);       // 128 x 132 floats, epilogue only

    int tid = threadIdx.x;
    int wid = tid >> 5, lane = tid & 31;
    int g = lane >> 2, t = lane & 3;
    int wm = wid & 3, wn = wid >> 2;
    int m0 = wm * 32, n0 = wn * 64;
    int base = blockIdx.x * 128;

    if (DO_LN && tid < 128) {
        sbias[tid] = __ldg(bias + tid);
        sgam[tid]  = __ldg(gamma + tid);
        sbet[tid]  = __ldg(beta + tid);
    }

    // loader indices
    int arow = tid >> 3;            // 0..31 (x4 over t-iters -> 128 rows)... see loop
    // A: 1024 float4 per chunk: idx = tid + it*256 -> row = idx>>3 (0..127), j4 = idx&7
    // B: 1024 16B cp.async:     idx -> kk = idx>>5 (0..31), j4 = idx&31
    (void)arow;

    float4 ra[4];
    auto loadAreg = [&](int c) {
        #pragma unroll
        for (int it = 0; it < 4; it++) {
            int idx = tid + it * 256;
            int row = idx >> 3, j4 = idx & 7;
            int grow = base + row;
            int k = c * 32 + j4 * 4;
            float4 v = make_float4(0.f, 0.f, 0.f, 0.f);
            if (grow < n) {
                const float* P = (k < 128) ? (X + (size_t)grow * 128 + k)
                                           : (AGG + (size_t)grow * 128 + (k - 128));
                v = *reinterpret_cast<const float4*>(P);
            }
            v.x = tf32r(v.x); v.y = tf32r(v.y); v.z = tf32r(v.z); v.w = tf32r(v.w);
            ra[it] = v;
        }
    };
    auto storeA = [&](int st) {
        float* As = (float*)(sm + (st ? S_AS1 : S_AS0));
        #pragma unroll
        for (int it = 0; it < 4; it++) {
            int idx = tid + it * 256;
            int row = idx >> 3, j4 = idx & 7;
            *reinterpret_cast<float4*>(&As[row * 36 + j4 * 4]) = ra[it];
        }
    };
    auto preB = [&](int c, int st) {
        uint32_t bbase = smem_u32(sm + (st ? S_BS1 : S_BS0));
        #pragma unroll
        for (int it = 0; it < 4; it++) {
            int idx = tid + it * 256;
            int kk = idx >> 5, j4 = idx & 31;
            cp_async16(bbase + (uint32_t)(kk * 136 + j4 * 4) * 4,
                       Bw + (size_t)(c * 32 + kk) * 128 + j4 * 4);
        }
    };

    float acc[2][8][4];
    #pragma unroll
    for (int mt = 0; mt < 2; mt++)
        #pragma unroll
        for (int nt = 0; nt < 8; nt++)
            #pragma unroll
            for (int cc = 0; cc < 4; cc++) acc[mt][nt][cc] = 0.f;

    // prologue: chunk 0
    preB(0, 0);
    cp_commit();
    loadAreg(0);
    storeA(0);
    cp_wait0();
    __syncthreads();

    #pragma unroll 1
    for (int c = 0; c < NC; c++) {
        int st = c & 1;
        if (c + 1 < NC) {
            preB(c + 1, st ^ 1);
            cp_commit();
            loadAreg(c + 1);
        }
        // compute chunk c from buffers [st]
        {
            const float* As = (const float*)(sm + (st ? S_AS1 : S_AS0));
            const float* Bs = (const float*)(sm + (st ? S_BS1 : S_BS0));
            #pragma unroll
            for (int ks = 0; ks < 4; ks++) {
                int k0 = ks * 8;
                u32 af[2][4];
                #pragma unroll
                for (int mt = 0; mt < 2; mt++) {
                    int r = m0 + mt * 16 + g;
                    af[mt][0] = __float_as_uint(As[r * 36 + k0 + t]);
                    af[mt][1] = __float_as_uint(As[(r + 8) * 36 + k0 + t]);
                    af[mt][2] = __float_as_uint(As[r * 36 + k0 + t + 4]);
                    af[mt][3] = __float_as_uint(As[(r + 8) * 36 + k0 + t + 4]);
                }
                #pragma unroll
                for (int nt = 0; nt < 8; nt++) {
                    int ccol = n0 + nt * 8 + g;
                    u32 bf[2];
                    bf[0] = __float_as_uint(Bs[(k0 + t) * 136 + ccol]);
                    bf[1] = __float_as_uint(Bs[(k0 + t + 4) * 136 + ccol]);
                    mma_tf32(acc[0][nt], af[0], bf);
                    mma_tf32(acc[1][nt], af[1], bf);
                }
            }
        }
        if (c + 1 < NC) {
            __syncthreads();            // all warps done with buffer st^1 from c-1
            storeA(st ^ 1);
            cp_wait0();
            __syncthreads();
        }
    }
    __syncthreads();   // compute done everywhere before srow overlays As/Bs

    // ---- epilogue phase 0: fragments -> srow staging ----
    #pragma unroll
    for (int mt = 0; mt < 2; mt++) {
        int r0 = m0 + mt * 16 + g;
        #pragma unroll
        for (int nt = 0; nt < 8; nt++) {
            int col = n0 + nt * 8 + 2 * t;
            *reinterpret_cast<float2*>(&srow[r0 * 132 + col]) =
                make_float2(acc[mt][nt][0], acc[mt][nt][1]);
            *reinterpret_cast<float2*>(&srow[(r0 + 8) * 132 + col]) =
                make_float2(acc[mt][nt][2], acc[mt][nt][3]);
        }
    }
    __syncthreads();

    // ---- epilogue phase 1: per-row LN stats (thread = row) ----
    if (DO_LN && tid < 128) {
        float s1 = 0.f, s2 = 0.f;
        #pragma unroll
        for (int j = 0; j < 128; j += 4) {
            float4 v = *reinterpret_cast<const float4*>(&srow[tid * 132 + j]);
            v.x += sbias[j + 0]; v.y += sbias[j + 1];
            v.z += sbias[j + 2]; v.w += sbias[j + 3];
            *reinterpret_cast<float4*>(&srow[tid * 132 + j]) = v;
            s1 += (v.x + v.y) + (v.z + v.w);
            s2 += (v.x * v.x + v.y * v.y) + (v.z * v.z + v.w * v.w);
        }
        float mu = s1 * (1.0f / 128.0f);
        float var = s2 * (1.0f / 128.0f) - mu * mu;
        smu[tid] = mu;
        srs[tid] = rsqrtf(var + EPS_LN);
    }
    __syncthreads();

    // ---- epilogue phase 2: coalesced stores ----
    for (int r = wid; r < 128; r += 8) {
        int row = base + r;
        if (row >= n) continue;
        float4 v = *reinterpret_cast<const float4*>(&srow[r * 132 + lane * 4]);
        if (DO_LN) {
            float mu = smu[r], rs = srs[r];
            float4 gg = *reinterpret_cast<const float4*>(&sgam[lane * 4]);
            float4 ee = *reinterpret_cast<const float4*>(&sbet[lane * 4]);
            v.x = fmaxf((v.x - mu) * rs * gg.x + ee.x, 0.f);
            v.y = fmaxf((v.y - mu) * rs * gg.y + ee.y, 0.f);
            v.z = fmaxf((v.z - mu) * rs * gg.z + ee.z, 0.f);
            v.w = fmaxf((v.w - mu) * rs * gg.w + ee.w, 0.f);
        }
        *reinterpret_cast<float4*>(out + (size_t)row * 128 + lane * 4) = v;
    }
}

// ---------------- final: out = log_softmax(t2[:, :64] + agg64 + b2) --------
__global__ void __launch_bounds__(256) k_final(
    const float* __restrict__ t2, const float* __restrict__ agg,
    const float* __restrict__ b2, float* __restrict__ out, int n)
{
    int w = (blockIdx.x * 256 + threadIdx.x) >> 5;
    int lane = threadIdx.x & 31;
    if (w >= n) return;
    float va = t2[(size_t)w * 128 + lane]      + agg[(size_t)w * 64 + lane]      + __ldg(&b2[lane]);
    float vb = t2[(size_t)w * 128 + 32 + lane] + agg[(size_t)w * 64 + 32 + lane] + __ldg(&b2[32 + lane]);
    float m = fmaxf(va, vb);
    #pragma unroll
    for (int o = 16; o > 0; o >>= 1)
        m = fmaxf(m, __shfl_xor_sync(0xffffffffu, m, o));
    float se = expf(va - m) + expf(vb - m);
    #pragma unroll
    for (int o = 16; o > 0; o >>= 1)
        se += __shfl_xor_sync(0xffffffffu, se, o);
    float ls = m + logf(se);
    out[(size_t)w * 64 + lane]      = va - ls;
    out[(size_t)w * 64 + 32 + lane] = vb - ls;
}

// ---------------- launcher --------------------------------------------------
extern "C" void kernel_launch(void* const* d_in, const int* in_sizes, int n_in,
                              void* d_out, int out_size)
{
    const float* x   = (const float*)d_in[0];
    const int*  esrc = (const int*)d_in[1];
    const int*  edst = (const int*)d_in[2];
    const float* Wr0 = (const float*)d_in[3];
    const float* Wn0 = (const float*)d_in[4];
    const float* b0  = (const float*)d_in[5];
    const float* g0  = (const float*)d_in[6];
    const float* be0 = (const float*)d_in[7];
    const float* Wr1 = (const float*)d_in[8];
    const float* Wn1 = (const float*)d_in[9];
    const float* b1  = (const float*)d_in[10];
    const float* g1  = (const float*)d_in[11];
    const float* be1 = (const float*)d_in[12];
    const float* Wr2 = (const float*)d_in[13];
    const float* Wn2 = (const float*)d_in[14];
    const float* b2  = (const float*)d_in[15];
    float* out = (float*)d_out;

    int n = in_sizes[0] / 128;
    int E = in_sizes[1];
    if (n > MAXN) n = MAXN;
    if (E > MAXE) E = MAXE;

    int *degi, *off, *cursor, *csr;
    float *rdeg, *agg, *hA, *hB, *Bw0, *Bw1, *Bw2;
    cudaGetSymbolAddress((void**)&degi,   g_degi);
    cudaGetSymbolAddress((void**)&off,    g_off);
    cudaGetSymbolAddress((void**)&cursor, g_cursor);
    cudaGetSymbolAddress((void**)&csr,    g_csr);
    cudaGetSymbolAddress((void**)&rdeg,   g_rdeg);
    cudaGetSymbolAddress((void**)&agg,    g_agg);
    cudaGetSymbolAddress((void**)&hA,     g_hA);
    cudaGetSymbolAddress((void**)&hB,     g_hB);
    cudaGetSymbolAddress((void**)&Bw0,    g_Bw0);
    cudaGetSymbolAddress((void**)&Bw1,    g_Bw1);
    cudaGetSymbolAddress((void**)&Bw2,    g_Bw2);

    cudaFuncSetAttribute(k_gemm_mma<256, true>,  cudaFuncAttributeMaxDynamicSharedMemorySize, S_TOTAL);
    cudaFuncSetAttribute(k_gemm_mma<128, false>, cudaFuncAttributeMaxDynamicSharedMemorySize, S_TOTAL);

    int gb = (n + 127) / 128;
    int gw = (n + 7) / 8;

    // CSR build + weight prep
    k_zeroi<<<(n + 255) / 256, 256>>>(degi, n);
    k_count<<<(E + 255) / 256, 256>>>(edst, degi, E);
    k_scan<<<1, 1024>>>(degi, off, cursor, rdeg, n);
    k_fill<<<(E + 255) / 256, 256>>>(esrc, edst, cursor, csr, E);
    k_prep01<<<128, 256>>>(Wr0, Wn0, Bw0);
    k_prep01<<<128, 256>>>(Wr1, Wn1, Bw1);
    k_prep2<<<64, 256>>>(Wr2, Wn2, Bw2);

    // layer 0
    k_agg128<<<gw, 256>>>(x, csr, off, rdeg, agg, n);
    k_gemm_mma<256, true><<<gb, 256, S_TOTAL>>>(x, agg, Bw0, b0, g0, be0, hA, n);

    // layer 1
    k_agg128<<<gw, 256>>>(hA, csr, off, rdeg, agg, n);
    k_gemm_mma<256, true><<<gb, 256, S_TOTAL>>>(hA, agg, Bw1, b1, g1, be1, hB, n);

    // layer 2: t2 = h1 @ [Wr2 | Wn2]; aggregate the Wn half post-GEMM
    k_gemm_mma<128, false><<<gb, 256, S_TOTAL>>>(hB, hB, Bw2, b2, g0, be0, hA, n);
    k_agg64<<<gw, 256>>>(hA, csr, off, rdeg, agg, n);
    k_final<<<gw, 256>>>(hA, agg, b2, out, n);
}